// round 7
// baseline (speedup 1.0000x reference)
#include <cuda_runtime.h>
#include <cstdint>

#define B_DIM 64
#define S_DIM 512
#define W_DIM 256
#define D_DIM 768
#define N_DIM 96
#define MT 64
#define KT 64
#define NUM_KT 12
#define THREADS 256

#define A_ROW_STRIDE 272            // 64 fp32 * 4 + 16 pad
#define B_ROW_STRIDE 144            // 64 fp16 * 2 + 16 pad
#define A_STAGE 17408               // 64 * 272
#define B_STAGE 13824               // 96 * 144
#define SM_A 1024
#define SM_B (SM_A + 3 * A_STAGE)   // 53248
#define SMEM_TOTAL (SM_B + 3 * B_STAGE)  // 94720

// Pre-converted fp16 copy of clsw: [96][768] fp16 (row stride 1536 B)
__device__ __align__(16) unsigned char g_Bh[N_DIM * D_DIM * 2];

static __device__ __forceinline__ uint32_t smem_u32(const void* p) {
    uint32_t a;
    asm("{ .reg .u64 t; cvta.to.shared.u64 t, %1; cvt.u32.u64 %0, t; }" : "=r"(a) : "l"(p));
    return a;
}

static __device__ __forceinline__ void ldsm4(uint32_t* r, uint32_t addr) {
    asm volatile("ldmatrix.sync.aligned.m8n8.x4.shared.b16 {%0,%1,%2,%3}, [%4];"
                 : "=r"(r[0]), "=r"(r[1]), "=r"(r[2]), "=r"(r[3]) : "r"(addr));
}

static __device__ __forceinline__ void ldsm2(uint32_t* r, uint32_t addr) {
    asm volatile("ldmatrix.sync.aligned.m8n8.x2.shared.b16 {%0,%1}, [%2];"
                 : "=r"(r[0]), "=r"(r[1]) : "r"(addr));
}

static __device__ __forceinline__ void mma_f16(float* c, const uint32_t* a, const uint32_t* b) {
    asm volatile(
        "mma.sync.aligned.m16n8k16.row.col.f32.f16.f16.f32 "
        "{%0,%1,%2,%3}, {%4,%5,%6,%7}, {%8,%9}, {%0,%1,%2,%3};"
        : "+f"(c[0]), "+f"(c[1]), "+f"(c[2]), "+f"(c[3])
        : "r"(a[0]), "r"(a[1]), "r"(a[2]), "r"(a[3]), "r"(b[0]), "r"(b[1]));
}

static __device__ __forceinline__ uint32_t cvt_f16x2(float2 v) {
    uint32_t r;   // low half = lower-k element
    asm("cvt.rn.f16x2.f32 %0, %1, %2;" : "=r"(r) : "f"(v.y), "f"(v.x));
    return r;
}

static __device__ __forceinline__ uint2 cvt_f16x4(float4 v) {
    uint2 r;
    asm("cvt.rn.f16x2.f32 %0, %1, %2;" : "=r"(r.x) : "f"(v.y), "f"(v.x));
    asm("cvt.rn.f16x2.f32 %0, %1, %2;" : "=r"(r.y) : "f"(v.w), "f"(v.z));
    return r;
}

static __device__ __forceinline__ void cp16(uint32_t dst, const void* src) {
    asm volatile("cp.async.cg.shared.global [%0], [%1], 16;" :: "r"(dst), "l"(src) : "memory");
}

// ---------- kernel 1: convert clsw fp32 -> fp16 scratch ----------
__global__ void cvtB_kernel(const float* __restrict__ clsw) {
    int i = blockIdx.x * blockDim.x + threadIdx.x;   // 18432 float4 chunks
    float4 v = ((const float4*)clsw)[i];
    ((uint2*)g_Bh)[i] = cvt_f16x4(v);
}

// ---------- kernel 2: gathered GEMM, cp.async 3-stage ----------
__global__ __launch_bounds__(THREADS, 2)
void ner_hmma_kernel(const float* __restrict__ seq, const int* __restrict__ widx,
                     const float* __restrict__ clsb, float* __restrict__ out) {
    extern __shared__ char smem[];
    const uint32_t sb = smem_u32(smem);
    const int tid  = threadIdx.x;
    const int wid  = tid >> 5;
    const int lane = tid & 31;
    const int b  = blockIdx.x >> 2;
    const int w0 = (blockIdx.x & 3) * MT;

    int* idx_s = (int*)smem;
    if (tid < MT) idx_s[tid] = widx[b * W_DIM + w0 + tid];
    __syncthreads();

    // ---- cp.async task mappings ----
    // A: 64 rows x 16 chunks(16B) = 1024 tasks -> 4 per thread
    uint32_t aDst[4];
    const char* aSrc[4];
#pragma unroll
    for (int j = 0; j < 4; j++) {
        int u = tid + 256 * j;
        int row = u >> 4, ch = u & 15;
        aDst[j] = (uint32_t)row * A_ROW_STRIDE + (uint32_t)ch * 16;
        aSrc[j] = (const char*)(seq + ((size_t)b * S_DIM + idx_s[row]) * D_DIM) + ch * 16;
    }
    // B: 96 rows x 8 chunks(16B) = 768 tasks -> 3 per thread
    uint32_t bDst[3];
    const unsigned char* bSrc[3];
#pragma unroll
    for (int j = 0; j < 3; j++) {
        int u = tid + 256 * j;
        int row = u >> 3, ch = u & 7;
        bDst[j] = (uint32_t)row * B_ROW_STRIDE + (uint32_t)ch * 16;
        bSrc[j] = g_Bh + (size_t)row * (D_DIM * 2) + ch * 16;
    }

    // ---- consumer mapping: 2(M) x 4(N) warp grid, warp tile 32x24 ----
    const int wm = (wid & 1) * 32;
    const int wn = (wid >> 1) * 24;
    const int g  = lane >> 2;
    const int c2 = (lane & 3) * 2;

    uint32_t aOffC[2];
#pragma unroll
    for (int i = 0; i < 2; i++)
        aOffC[i] = (uint32_t)(wm + i * 16 + g) * A_ROW_STRIDE + (uint32_t)c2 * 4;

    const uint32_t bOff4 = (uint32_t)(wn + ((lane >> 4) << 3) + (lane & 7)) * B_ROW_STRIDE
                         + (((lane >> 3) & 1) << 4);
    const uint32_t bOff2 = (uint32_t)(wn + 16 + (lane & 7)) * B_ROW_STRIDE
                         + (((lane >> 3) & 1) << 4);

    float acc[6][4];
#pragma unroll
    for (int i = 0; i < 6; i++)
#pragma unroll
        for (int v = 0; v < 4; v++) acc[i][v] = 0.f;

    // ---- prologue: issue tiles 0 and 1 ----
#pragma unroll
    for (int t = 0; t < 2; t++) {
        const uint32_t aS = sb + SM_A + t * A_STAGE;
        const uint32_t bS = sb + SM_B + t * B_STAGE;
#pragma unroll
        for (int j = 0; j < 4; j++) cp16(aS + aDst[j], aSrc[j] + t * 256);
#pragma unroll
        for (int j = 0; j < 3; j++) cp16(bS + bDst[j], bSrc[j] + t * 128);
        asm volatile("cp.async.commit_group;" ::: "memory");
    }

#pragma unroll
    for (int t = 0; t < NUM_KT; t++) {
        // tile t arrived when at most 1 newer group is still pending
        if (t < NUM_KT - 1) asm volatile("cp.async.wait_group 1;" ::: "memory");
        else                asm volatile("cp.async.wait_group 0;" ::: "memory");
        __syncthreads();   // publishes tile t to all warps; guarantees stage (t+2)%3 free

        if (t + 2 < NUM_KT) {
            const int tn = t + 2;
            const uint32_t aS = sb + SM_A + (tn % 3) * A_STAGE;
            const uint32_t bS = sb + SM_B + (tn % 3) * B_STAGE;
#pragma unroll
            for (int j = 0; j < 4; j++) cp16(aS + aDst[j], aSrc[j] + tn * 256);
#pragma unroll
            for (int j = 0; j < 3; j++) cp16(bS + bDst[j], bSrc[j] + tn * 128);
            asm volatile("cp.async.commit_group;" ::: "memory");
        }

        const char* pA = smem + SM_A + (t % 3) * A_STAGE;
        const uint32_t sB = sb + SM_B + (t % 3) * B_STAGE;
#pragma unroll
        for (int ks = 0; ks < 4; ks++) {
            const uint32_t kA = (uint32_t)ks * 64;   // 16 fp32 = 64 B
            const uint32_t kB = (uint32_t)ks * 32;   // 16 fp16 = 32 B
            uint32_t af[2][4];
#pragma unroll
            for (int i = 0; i < 2; i++) {
                const char* p = pA + aOffC[i] + kA;
                af[i][0] = cvt_f16x2(*(const float2*)(p));
                af[i][1] = cvt_f16x2(*(const float2*)(p + 8 * A_ROW_STRIDE));
                af[i][2] = cvt_f16x2(*(const float2*)(p + 32));
                af[i][3] = cvt_f16x2(*(const float2*)(p + 8 * A_ROW_STRIDE + 32));
            }
            uint32_t bf[6];
            ldsm4(bf,     sB + bOff4 + kB);
            ldsm2(bf + 4, sB + bOff2 + kB);
#pragma unroll
            for (int i = 0; i < 2; i++)
#pragma unroll
                for (int j = 0; j < 3; j++)
                    mma_f16(acc[i * 3 + j], af[i], &bf[j * 2]);
        }
    }

    // ---- epilogue: scatter to out[a, b, w, c] ----
#pragma unroll
    for (int i = 0; i < 2; i++) {
#pragma unroll
        for (int j = 0; j < 3; j++) {
            const float* c = acc[i * 3 + j];
            const int n_base = wn + j * 8 + 2 * (lane & 3);
            const int m_base = wm + i * 16 + (lane >> 2);
#pragma unroll
            for (int v = 0; v < 4; v++) {
                const int n = n_base + (v & 1);
                const int m = m_base + (v >> 1) * 8;
                const int w = w0 + m;
                const int a_ = n / 3;
                const int c_ = n - a_ * 3;
                out[(size_t)a_ * (B_DIM * W_DIM * 3) + (size_t)b * (W_DIM * 3) + w * 3 + c_]
                    = c[v] + clsb[n];
            }
        }
    }
}

extern "C" void kernel_launch(void* const* d_in, const int* in_sizes, int n_in,
                              void* d_out, int out_size) {
    const float* seq  = (const float*)d_in[0];  // [B, S, D] fp32
    const int*   widx = (const int*)d_in[1];    // [B, W] int32
    const float* clsw = (const float*)d_in[2];  // [A*3, D] fp32
    const float* clsb = (const float*)d_in[3];  // [A*3] fp32
    float* out = (float*)d_out;                 // [A, B, W, 3] fp32

    cvtB_kernel<<<36, 512>>>(clsw);
    cudaFuncSetAttribute(ner_hmma_kernel, cudaFuncAttributeMaxDynamicSharedMemorySize, SMEM_TOTAL);
    ner_hmma_kernel<<<256, THREADS, SMEM_TOTAL>>>(seq, widx, clsb, out);
}

// round 9
// speedup vs baseline: 1.5405x; 1.5405x over previous
#include <cuda_runtime.h>
#include <cstdint>

#define B_DIM 64
#define S_DIM 512
#define W_DIM 256
#define D_DIM 768
#define N_DIM 96
#define MT 64
#define KT 128
#define NUM_KT 6
#define THREADS 256

#define RS 272                       // fp16 tile row stride: 128*2 + 16 pad
#define A_STAGE 17408                // 64 * 272
#define B_STAGE 26112                // 96 * 272
#define SM_A 1024
#define SM_B (SM_A + 2 * A_STAGE)    // 35840
#define SMEM_TOTAL (SM_B + 2 * B_STAGE)  // 88064

// Pre-converted fp16 copy of clsw: [96][768] fp16 (row stride 1536 B)
__device__ __align__(16) unsigned char g_Bh[N_DIM * D_DIM * 2];

static __device__ __forceinline__ uint32_t smem_u32(const void* p) {
    uint32_t a;
    asm("{ .reg .u64 t; cvta.to.shared.u64 t, %1; cvt.u32.u64 %0, t; }" : "=r"(a) : "l"(p));
    return a;
}

static __device__ __forceinline__ void ldsm4(uint32_t* r, uint32_t addr) {
    asm volatile("ldmatrix.sync.aligned.m8n8.x4.shared.b16 {%0,%1,%2,%3}, [%4];"
                 : "=r"(r[0]), "=r"(r[1]), "=r"(r[2]), "=r"(r[3]) : "r"(addr));
}

static __device__ __forceinline__ void ldsm2(uint32_t* r, uint32_t addr) {
    asm volatile("ldmatrix.sync.aligned.m8n8.x2.shared.b16 {%0,%1}, [%2];"
                 : "=r"(r[0]), "=r"(r[1]) : "r"(addr));
}

static __device__ __forceinline__ void mma_f16(float* c, const uint32_t* a, const uint32_t* b) {
    asm volatile(
        "mma.sync.aligned.m16n8k16.row.col.f32.f16.f16.f32 "
        "{%0,%1,%2,%3}, {%4,%5,%6,%7}, {%8,%9}, {%0,%1,%2,%3};"
        : "+f"(c[0]), "+f"(c[1]), "+f"(c[2]), "+f"(c[3])
        : "r"(a[0]), "r"(a[1]), "r"(a[2]), "r"(a[3]), "r"(b[0]), "r"(b[1]));
}

static __device__ __forceinline__ uint2 cvt_f16x4(float4 v) {
    uint2 r;   // low half of each word = lower-k element
    asm("cvt.rn.f16x2.f32 %0, %1, %2;" : "=r"(r.x) : "f"(v.y), "f"(v.x));
    asm("cvt.rn.f16x2.f32 %0, %1, %2;" : "=r"(r.y) : "f"(v.w), "f"(v.z));
    return r;
}

static __device__ __forceinline__ void cp16(uint32_t dst, const void* src) {
    asm volatile("cp.async.cg.shared.global [%0], [%1], 16;" :: "r"(dst), "l"(src) : "memory");
}

// ---------- kernel 1: convert clsw fp32 -> fp16 scratch ----------
__global__ void cvtB_kernel(const float* __restrict__ clsw) {
    int i = blockIdx.x * blockDim.x + threadIdx.x;   // 18432 float4 chunks
    float4 v = ((const float4*)clsw)[i];
    ((uint2*)g_Bh)[i] = cvt_f16x4(v);
}

// ---------- kernel 2: gathered GEMM, KT=128, B via cp.async ----------
__global__ __launch_bounds__(THREADS, 2)
void ner_hmma_kernel(const float* __restrict__ seq, const int* __restrict__ widx,
                     const float* __restrict__ clsb, float* __restrict__ out) {
    extern __shared__ char smem[];
    const uint32_t sb = smem_u32(smem);
    const int tid  = threadIdx.x;
    const int wid  = tid >> 5;
    const int lane = tid & 31;
    const int b  = blockIdx.x >> 2;
    const int w0 = (blockIdx.x & 3) * MT;

    int* idx_s = (int*)smem;
    if (tid < MT) idx_s[tid] = widx[b * W_DIM + w0 + tid];
    __syncthreads();

    // ---- A producer: 64 rows x 32 float4-chunks = 2048 tasks -> 8/thread ----
    // warp w, task j: row = w + 8j (whole warp on one row), ch = lane
    const float* aSrc[8];
    uint32_t aDst[8];
#pragma unroll
    for (int j = 0; j < 8; j++) {
        int u = tid + 256 * j;
        int row = u >> 5, ch = u & 31;
        aSrc[j] = seq + ((size_t)b * S_DIM + idx_s[row]) * D_DIM + ch * 4;
        aDst[j] = (uint32_t)row * RS + (uint32_t)ch * 8;
    }
    // ---- B producer (cp.async): 96 rows x 16 chunks(16B) = 1536 -> 6/thread ----
    const unsigned char* bSrc[6];
    uint32_t bDst[6];
#pragma unroll
    for (int j = 0; j < 6; j++) {
        int u = tid + 256 * j;
        int row = u >> 4, ch = u & 15;
        bSrc[j] = g_Bh + (size_t)row * (D_DIM * 2) + ch * 16;
        bDst[j] = (uint32_t)row * RS + (uint32_t)ch * 16;
    }

    // ---- consumer mapping: 2(M) x 4(N) warp grid, warp tile 32x24 ----
    const int wm = (wid & 1) * 32;
    const int wn = (wid >> 1) * 24;
    const uint32_t aOff  = (uint32_t)(wm + (lane & 15)) * RS + ((lane >> 4) << 4);
    const uint32_t bOff4 = (uint32_t)(wn + ((lane >> 4) << 3) + (lane & 7)) * RS
                         + (((lane >> 3) & 1) << 4);
    const uint32_t bOff2 = (uint32_t)(wn + 16 + (lane & 7)) * RS
                         + (((lane >> 3) & 1) << 4);

    float acc[6][4];
#pragma unroll
    for (int i = 0; i < 6; i++)
#pragma unroll
        for (int v = 0; v < 4; v++) acc[i][v] = 0.f;

    // ---- prologue: A(0) -> regs, B(0) -> cp.async stage 0 ----
    float4 ra[8];
#pragma unroll
    for (int j = 0; j < 8; j++) ra[j] = *(const float4*)(aSrc[j]);
#pragma unroll
    for (int j = 0; j < 6; j++) cp16(sb + SM_B + bDst[j], bSrc[j]);
    asm volatile("cp.async.commit_group;" ::: "memory");

#pragma unroll
    for (int t = 0; t < NUM_KT; t++) {
        const int p = t & 1;
        char* bufA = smem + SM_A + p * A_STAGE;

        // 1. convert + store A(t)
#pragma unroll
        for (int j = 0; j < 8; j++) *(uint2*)(bufA + aDst[j]) = cvt_f16x4(ra[j]);

        // 2. prefetch A(t+1) into regs (one full tile of latency cover)
        if (t + 1 < NUM_KT) {
            const int kg = (t + 1) * KT;
#pragma unroll
            for (int j = 0; j < 8; j++) ra[j] = *(const float4*)(aSrc[j] + kg);
        }

        // 3. drain B(t) (only pending group), 4. publish A(t)+B(t) to all warps
        asm volatile("cp.async.wait_group 0;" ::: "memory");
        __syncthreads();

        // 5. issue B(t+1) into the stage compute(t-1) finished with
        if (t + 1 < NUM_KT) {
            const uint32_t bS = sb + SM_B + ((t + 1) & 1) * B_STAGE;
            const int kb = (t + 1) * (KT * 2);
#pragma unroll
            for (int j = 0; j < 6; j++) cp16(bS + bDst[j], bSrc[j] + kb);
            asm volatile("cp.async.commit_group;" ::: "memory");
        }

        // 6. compute(t): 8 k-steps
        const uint32_t sA = sb + SM_A + p * A_STAGE;
        const uint32_t sB = sb + SM_B + p * B_STAGE;
#pragma unroll
        for (int ks = 0; ks < 8; ks++) {
            const uint32_t k0b = (uint32_t)ks * 32;   // 16 fp16 = 32 B
            uint32_t af[2][4];
#pragma unroll
            for (int i = 0; i < 2; i++)
                ldsm4(af[i], sA + aOff + i * (16 * RS) + k0b);
            uint32_t bf[6];
            ldsm4(bf,     sB + bOff4 + k0b);
            ldsm2(bf + 4, sB + bOff2 + k0b);
#pragma unroll
            for (int i = 0; i < 2; i++)
#pragma unroll
                for (int j = 0; j < 3; j++)
                    mma_f16(acc[i * 3 + j], af[i], &bf[j * 2]);
        }
    }

    // ---- epilogue: scatter to out[a, b, w, c] ----
#pragma unroll
    for (int i = 0; i < 2; i++) {
#pragma unroll
        for (int j = 0; j < 3; j++) {
            const float* c = acc[i * 3 + j];
            const int n_base = wn + j * 8 + 2 * (lane & 3);
            const int m_base = wm + i * 16 + (lane >> 2);
#pragma unroll
            for (int v = 0; v < 4; v++) {
                const int n = n_base + (v & 1);
                const int m = m_base + (v >> 1) * 8;
                const int w = w0 + m;
                const int a_ = n / 3;
                const int c_ = n - a_ * 3;
                out[(size_t)a_ * (B_DIM * W_DIM * 3) + (size_t)b * (W_DIM * 3) + w * 3 + c_]
                    = c[v] + clsb[n];
            }
        }
    }
}

extern "C" void kernel_launch(void* const* d_in, const int* in_sizes, int n_in,
                              void* d_out, int out_size) {
    const float* seq  = (const float*)d_in[0];  // [B, S, D] fp32
    const int*   widx = (const int*)d_in[1];    // [B, W] int32
    const float* clsw = (const float*)d_in[2];  // [A*3, D] fp32
    const float* clsb = (const float*)d_in[3];  // [A*3] fp32
    float* out = (float*)d_out;                 // [A, B, W, 3] fp32

    cvtB_kernel<<<36, 512>>>(clsw);
    cudaFuncSetAttribute(ner_hmma_kernel, cudaFuncAttributeMaxDynamicSharedMemorySize, SMEM_TOTAL);
    ner_hmma_kernel<<<256, THREADS, SMEM_TOTAL>>>(seq, widx, clsb, out);
}